// round 7
// baseline (speedup 1.0000x reference)
#include <cuda_runtime.h>
#include <cuda_bf16.h>

#define N_NODES 50000
#define E_CAP   700000
#define HEADS   4
#define OUT_CH  16
#define OUT_NEU 32
#define IN_CH   128
#define HID     128   // HEADS*OUT_NEU

// ---- output layout (flat concat of reference return tuple, fp32) ----
#define OFF_OUT    0
#define OFF_IXZ    (N_NODES * 64)                  // 3,200,000
#define OFF_SCALAR (OFF_IXZ + N_NODES)             // 3,250,000
#define OFF_MEAN   (OFF_SCALAR + 1)                // 3,250,001 (ODD -> no vector stores!)
#define OFF_STD    (OFF_MEAN + N_NODES * 64)       // 6,450,001 (ODD -> no vector stores!)

// ---- scratch (device globals; no allocation allowed) ----
__device__ __align__(16) float g_h[N_NODES * HID];     // node features after GEMM
__device__ __align__(16) float g_agg[N_NODES * HID];   // UNNORMALIZED segment-sum
__device__ __align__(16) float g_aI[N_NODES * HEADS];  // h . att_i (dst term)
__device__ __align__(16) float g_aJ[N_NODES * HEADS];  // h . att_j (src term)
__device__ __align__(16) float g_denom[N_NODES * HEADS];

__device__ __forceinline__ void red_add_v4(float* gptr, float a, float b, float c, float d) {
    asm volatile("red.global.add.v4.f32 [%0], {%1, %2, %3, %4};"
                 :: "l"(gptr), "f"(a), "f"(b), "f"(c), "f"(d) : "memory");
}
__device__ __forceinline__ void red_add_f32(float* gptr, float a) {
    asm volatile("red.global.add.f32 [%0], %1;" :: "l"(gptr), "f"(a) : "memory");
}

__device__ __forceinline__ float lrelu(float a) {
    return a > 0.0f ? a : 0.2f * a;
}

// ---------------------------------------------------------------- K0a: zero agg
__global__ void zero_agg_kernel() {
    int i = blockIdx.x * blockDim.x + threadIdx.x;
    int stride = gridDim.x * blockDim.x;
    float4 z = make_float4(0.f, 0.f, 0.f, 0.f);
    for (int k = i; k < N_NODES * HID / 4; k += stride)
        ((float4*)g_agg)[k] = z;
}
// ---------------------------------------------------------------- K0b: zero denom
__global__ void zero_denom_kernel() {
    int i = blockIdx.x * blockDim.x + threadIdx.x;
    if (i < N_NODES)
        ((float4*)g_denom)[i] = make_float4(0.f, 0.f, 0.f, 0.f);
}

// ------------------------------------------- K1: GEMM + per-node attention dots
#define GEMM_ROWS 16
#define XT_PITCH  20
#define GEMM_SMEM ((IN_CH * HID + IN_CH * XT_PITCH) * 4)

__global__ __launch_bounds__(256) void gemm_kernel(
    const float* __restrict__ x, const float* __restrict__ w,
    const float* __restrict__ att)
{
    extern __shared__ float sm[];
    float* sW  = sm;                 // [k][col]
    float* sXT = sm + IN_CH * HID;   // [k][row] pitch 20

    const int tid  = threadIdx.x;
    const int row0 = blockIdx.x * GEMM_ROWS;

    for (int i = tid; i < IN_CH * HID; i += 256) sW[i] = w[i];
    for (int i = tid; i < GEMM_ROWS * IN_CH; i += 256) {
        int r = i >> 7, k = i & 127;
        sXT[k * XT_PITCH + r] = x[(row0 + r) * IN_CH + k];
    }
    __syncthreads();

    const int col = tid & 127;
    const int rh  = tid >> 7;      // 0 or 1

    float acc[8];
#pragma unroll
    for (int j = 0; j < 8; j++) acc[j] = 0.0f;

#pragma unroll 4
    for (int k = 0; k < IN_CH; k++) {
        const float wv = sW[k * HID + col];
        const float4 a0 = *(const float4*)&sXT[k * XT_PITCH + rh * 8];
        const float4 a1 = *(const float4*)&sXT[k * XT_PITCH + rh * 8 + 4];
        acc[0] = fmaf(a0.x, wv, acc[0]);
        acc[1] = fmaf(a0.y, wv, acc[1]);
        acc[2] = fmaf(a0.z, wv, acc[2]);
        acc[3] = fmaf(a0.w, wv, acc[3]);
        acc[4] = fmaf(a1.x, wv, acc[4]);
        acc[5] = fmaf(a1.y, wv, acc[5]);
        acc[6] = fmaf(a1.z, wv, acc[6]);
        acc[7] = fmaf(a1.w, wv, acc[7]);
    }

    const int head = col >> 5;
    const int lane = col & 31;
    const float attI = att[head * 64 + lane];
    const float attJ = att[head * 64 + 32 + lane];

#pragma unroll
    for (int j = 0; j < 8; j++) {
        const int row = row0 + rh * 8 + j;
        g_h[row * HID + col] = acc[j];
        float sI = acc[j] * attI;
        float sJ = acc[j] * attJ;
#pragma unroll
        for (int o = 16; o; o >>= 1) {
            sI += __shfl_xor_sync(0xffffffffu, sI, o);
            sJ += __shfl_xor_sync(0xffffffffu, sJ, o);
        }
        if (lane == 0) {
            g_aI[row * HEADS + head] = sI;
            g_aJ[row * HEADS + head] = sJ;
        }
    }
}

// ------- K2: FUSED edge pass: e = exp(leaky(aI[d]+aJ[s]));
//         agg[dst] += e * h[src]   (unnormalized)
//         denom[dst] += e          (one lane per head)
// 32 threads per edge; lane -> (head = lane>>3, float4-chunk = lane&7)
// No max subtraction: e/(denom+eps) is scale invariant (validated R4-R6).
__global__ void edge_fused(const int* __restrict__ src,
                           const int* __restrict__ dst, int E)
{
    int g = blockIdx.x * blockDim.x + threadIdx.x;
    int e = g >> 5;
    if (e >= E) return;
    int lane = g & 31;
    int s = src[e], d = dst[e];           // broadcast loads (same per warp)
    int head = lane >> 3;
    float aih = __ldg(&g_aI[d * 4 + head]);   // broadcast within 8-lane group
    float ajh = __ldg(&g_aJ[s * 4 + head]);
    float ev = __expf(lrelu(aih + ajh));
    float4 hv = ((const float4*)g_h)[s * 32 + lane];  // lane*4 == head*32 + q*4
    red_add_v4(&g_agg[d * HID + lane * 4],
               hv.x * ev, hv.y * ev, hv.z * ev, hv.w * ev);
    if ((lane & 7) == 0)                  // lanes 0,8,16,24: one red per head
        red_add_f32(&g_denom[d * 4 + head], ev);
}

// ----------------------------------- K3: VIB epilogue (+ normalization) + outputs
// warp per node: lane -> (head = lane>>3, cc = lane&7 handles c=cc and c=cc+8)
__global__ __launch_bounds__(256) void finalize_kernel(
    const float* __restrict__ bias, float* __restrict__ out)
{
    int warp = threadIdx.x >> 5, lane = threadIdx.x & 31;
    int n = blockIdx.x * 8 + warp;
    if (n >= N_NODES) return;
    int head = lane >> 3, cc = lane & 7;

    const float inv = 1.0f / (__ldg(&g_denom[n * 4 + head]) + 1e-16f);

    float kl = 0.0f;
#pragma unroll
    for (int t = 0; t < 2; t++) {
        int c = cc + t * 8;
        float mv = g_agg[n * HID + head * 32 + c] * inv + bias[head * 32 + c];
        float sp = g_agg[n * HID + head * 32 + 16 + c] * inv + bias[head * 32 + 16 + c] - 5.0f;
        // stable softplus: max(x,0) + log1p(exp(-|x|))
        float st = fmaxf(sp, 0.0f) + log1pf(expf(-fabsf(sp))) + 1e-10f;
        kl += -logf(st) + 0.5f * (st * st + mv * mv) - 0.5f;
        out[OFF_OUT  + n * 64 + head * 16 + c] = mv;
        out[OFF_MEAN + n * 64 + head * 16 + c] = mv;
        out[OFF_STD  + n * 64 + head * 16 + c] = st;
    }
#pragma unroll
    for (int o = 16; o; o >>= 1) kl += __shfl_xor_sync(0xffffffffu, kl, o);
    if (lane == 0) out[OFF_IXZ + n] = kl * 0.25f;
    if (blockIdx.x == 0 && threadIdx.x == 0) out[OFF_SCALAR] = 0.0f;
}

// ---------------------------------------------------------------- launch
extern "C" void kernel_launch(void* const* d_in, const int* in_sizes, int n_in,
                              void* d_out, int out_size)
{
    const float* x    = (const float*)d_in[0];
    const int*   ei   = (const int*)d_in[1];
    const float* w    = (const float*)d_in[2];
    const float* att  = (const float*)d_in[3];
    const float* bias = (const float*)d_in[4];
    float* out = (float*)d_out;

    const int E = in_sizes[1] / 2;
    const int* src = ei;
    const int* dst = ei + E;

    cudaFuncSetAttribute(gemm_kernel,
                         cudaFuncAttributeMaxDynamicSharedMemorySize, GEMM_SMEM);

    // launch order chosen so edge_fused is the 4th launch (ncu profiles #4)
    zero_agg_kernel<<<512, 256>>>();
    zero_denom_kernel<<<(N_NODES + 255) / 256, 256>>>();
    gemm_kernel<<<N_NODES / GEMM_ROWS, 256, GEMM_SMEM>>>(x, w, att);
    edge_fused<<<(E * 32 + 255) / 256, 256>>>(src, dst, E);
    finalize_kernel<<<(N_NODES + 7) / 8, 256>>>(bias, out);
}